// round 3
// baseline (speedup 1.0000x reference)
#include <cuda_runtime.h>
#include <math.h>

#define B_  16
#define TO_ 2048
#define TI_ 2048
#define D_  64
#define BM  64
#define BN  64
#define NTHREADS 256
#define KT_STRIDE 65   // pad to break transpose-store bank conflicts

// dynamic smem layout (floats):
//   sQ : BM * D_            = 4096
//   sKt: D_ * KT_STRIDE     = 4160   (reused as P[BM][KT_STRIDE] after GEMM1)
//   sV : BN * D_            = 4096
// total = 12352 floats = 49408 bytes (> 48K static limit -> dynamic + attribute)

__global__ __launch_bounds__(NTHREADS, 2)
void attn_fwd(const float* __restrict__ Q, const float* __restrict__ K,
              const float* __restrict__ V, const int* __restrict__ M,
              float* __restrict__ O)
{
    extern __shared__ float smem[];
    float* sQ  = smem;                       // [BM][D_]
    float* sKt = smem + BM * D_;             // [D_][KT_STRIDE] / P: [BM][KT_STRIDE]
    float* sV  = sKt + D_ * KT_STRIDE;       // [BN][D_]

    const int b   = blockIdx.y;
    const int q0  = blockIdx.x * BM;
    const int tid = threadIdx.x;
    const int tx  = tid & 15;                // 0..15  (columns / d-dims)
    const int ty  = tid >> 4;                // 0..15  (rows)
    const int r0  = ty << 2;                 // 4 query rows per thread
    const int c0  = tx << 2;                 // 4 kv cols / 4 d dims per thread

    const float* Qb = Q + ((size_t)b * TO_ + q0) * D_;
    const float* Kb = K + (size_t)b * TI_ * D_;
    const float* Vb = V + (size_t)b * TI_ * D_;
    const int*   Mb = M + ((size_t)b * TO_ + q0) * TI_;

    // ---- load Q tile (64x64 f32), coalesced float4 ----
#pragma unroll
    for (int i = 0; i < 4; i++) {
        int idx = tid + i * NTHREADS;        // float4 index 0..1023
        int row = idx >> 4;                  // 16 float4 per row
        int col = (idx & 15) << 2;
        *(float4*)&sQ[row * D_ + col] = *(const float4*)&Qb[(size_t)row * D_ + col];
    }

    float acc[4][4];
#pragma unroll
    for (int j = 0; j < 4; j++)
#pragma unroll
        for (int i = 0; i < 4; i++) acc[j][i] = 0.f;
    float m_i[4] = { -INFINITY, -INFINITY, -INFINITY, -INFINITY };
    float l_i[4] = { 0.f, 0.f, 0.f, 0.f };

    for (int kv0 = 0; kv0 < TI_; kv0 += BN) {
        __syncthreads();   // prior GEMM2 readers done; Q store visible on 1st iter

        // ---- stage K transposed (sKt[kdim][kv]) and V (sV[kv][kdim]) ----
#pragma unroll
        for (int i = 0; i < 4; i++) {
            int idx = tid + i * NTHREADS;
            int row = idx >> 4;              // kv index in tile
            int col = (idx & 15) << 2;       // kdim base
            const float4 k4 = *(const float4*)&Kb[(size_t)(kv0 + row) * D_ + col];
            sKt[(col + 0) * KT_STRIDE + row] = k4.x;
            sKt[(col + 1) * KT_STRIDE + row] = k4.y;
            sKt[(col + 2) * KT_STRIDE + row] = k4.z;
            sKt[(col + 3) * KT_STRIDE + row] = k4.w;
            *(float4*)&sV[row * D_ + col] =
                *(const float4*)&Vb[(size_t)(kv0 + row) * D_ + col];
        }
        __syncthreads();

        // ---- GEMM1: s[j][i] = sum_k Q[r0+j][k] * K[c0+i][k] ----
        float s[4][4];
#pragma unroll
        for (int j = 0; j < 4; j++)
#pragma unroll
            for (int i = 0; i < 4; i++) s[j][i] = 0.f;

#pragma unroll
        for (int kk = 0; kk < D_; kk += 4) {
            float aq[4][4];
#pragma unroll
            for (int j = 0; j < 4; j++) {
                const float4 t4 = *(const float4*)&sQ[(r0 + j) * D_ + kk];
                aq[j][0] = t4.x; aq[j][1] = t4.y; aq[j][2] = t4.z; aq[j][3] = t4.w;
            }
            float bk[4][4];
#pragma unroll
            for (int t = 0; t < 4; t++)
#pragma unroll
                for (int i = 0; i < 4; i++)
                    bk[t][i] = sKt[(kk + t) * KT_STRIDE + c0 + i];
#pragma unroll
            for (int j = 0; j < 4; j++)
#pragma unroll
                for (int i = 0; i < 4; i++)
#pragma unroll
                    for (int t = 0; t < 4; t++)
                        s[j][i] = fmaf(aq[j][t], bk[t][i], s[j][i]);
        }

        // ---- scale + mask (mask straight from gmem, int4) ----
#pragma unroll
        for (int j = 0; j < 4; j++) {
            const int4 mm = *(const int4*)&Mb[(size_t)(r0 + j) * TI_ + kv0 + c0];
            s[j][0] = (mm.x == 0) ? -1e10f : s[j][0] * 0.125f;
            s[j][1] = (mm.y == 0) ? -1e10f : s[j][1] * 0.125f;
            s[j][2] = (mm.z == 0) ? -1e10f : s[j][2] * 0.125f;
            s[j][3] = (mm.w == 0) ? -1e10f : s[j][3] * 0.125f;
        }

        // ---- online softmax (reduce across 16-lane tx group) ----
        float p[4][4];
#pragma unroll
        for (int j = 0; j < 4; j++) {
            float mloc = fmaxf(fmaxf(s[j][0], s[j][1]), fmaxf(s[j][2], s[j][3]));
#pragma unroll
            for (int off = 8; off >= 1; off >>= 1)
                mloc = fmaxf(mloc, __shfl_xor_sync(0xffffffffu, mloc, off));
            const float mn = fmaxf(m_i[j], mloc);
            const float sc = __expf(m_i[j] - mn);   // exp(-inf)=0 on first tile
            m_i[j] = mn;
            float ps = 0.f;
#pragma unroll
            for (int i = 0; i < 4; i++) {
                p[j][i] = __expf(s[j][i] - mn);
                ps += p[j][i];
            }
#pragma unroll
            for (int off = 8; off >= 1; off >>= 1)
                ps += __shfl_xor_sync(0xffffffffu, ps, off);
            l_i[j] = l_i[j] * sc + ps;
#pragma unroll
            for (int i = 0; i < 4; i++) acc[j][i] *= sc;
        }

        __syncthreads();   // everyone done reading sKt as K^T
        // ---- stage P into the Kt buffer, viewed as [BM][KT_STRIDE] ----
#pragma unroll
        for (int j = 0; j < 4; j++)
#pragma unroll
            for (int i = 0; i < 4; i++)
                sKt[(r0 + j) * KT_STRIDE + c0 + i] = p[j][i];
        __syncthreads();

        // ---- GEMM2: acc[j][i] += sum_c P[r0+j][c] * V[c][c0+i] ----
#pragma unroll
        for (int cc = 0; cc < BN; cc += 4) {
            float pj[4][4];
#pragma unroll
            for (int j = 0; j < 4; j++)
#pragma unroll
                for (int t = 0; t < 4; t++)
                    pj[j][t] = sKt[(r0 + j) * KT_STRIDE + cc + t];
            float vv[4][4];
#pragma unroll
            for (int t = 0; t < 4; t++) {
                const float4 t4 = *(const float4*)&sV[(cc + t) * D_ + c0];
                vv[t][0] = t4.x; vv[t][1] = t4.y; vv[t][2] = t4.z; vv[t][3] = t4.w;
            }
#pragma unroll
            for (int j = 0; j < 4; j++)
#pragma unroll
                for (int i = 0; i < 4; i++)
#pragma unroll
                    for (int t = 0; t < 4; t++)
                        acc[j][i] = fmaf(pj[j][t], vv[t][i], acc[j][i]);
        }
    }

    // ---- normalize and write out ----
    float* Ob = O + ((size_t)b * TO_ + q0) * D_;
#pragma unroll
    for (int j = 0; j < 4; j++) {
        const float inv = 1.f / l_i[j];
        float4 o4;
        o4.x = acc[j][0] * inv;
        o4.y = acc[j][1] * inv;
        o4.z = acc[j][2] * inv;
        o4.w = acc[j][3] * inv;
        *(float4*)&Ob[(size_t)(r0 + j) * D_ + c0] = o4;
    }
}

extern "C" void kernel_launch(void* const* d_in, const int* in_sizes, int n_in,
                              void* d_out, int out_size) {
    const float* q = (const float*)d_in[0];
    const float* k = (const float*)d_in[1];
    const float* v = (const float*)d_in[2];
    const int*   m = (const int*)d_in[3];
    float* o = (float*)d_out;

    const size_t shmem = (size_t)(BM * D_ + D_ * KT_STRIDE + BN * D_) * sizeof(float);
    cudaFuncSetAttribute(attn_fwd, cudaFuncAttributeMaxDynamicSharedMemorySize, (int)shmem);

    dim3 grid(TO_ / BM, B_);
    attn_fwd<<<grid, NTHREADS, shmem>>>(q, k, v, m, o);
}

// round 9
// speedup vs baseline: 4.4276x; 4.4276x over previous
#include <cuda_runtime.h>
#include <math.h>
#include <stdint.h>

#define B_   16
#define TO_  2048
#define TI_  2048
#define D_   64
#define BM   128
#define BN   64
#define NTH  256
#define NT   (TI_/BN)

// smem layout (bytes). K/V rows padded to 68 words (272B, 16B-aligned, good banks)
// buf b: K at b*34816 (64*272=17408), V at b*34816+17408
// mask:  at 69632, 128 rows * 272B = 34816
#define SM_M       69632
#define SMEM_BYTES (69632 + 34816)   // 104448

#define CPA16(dst, src) asm volatile("cp.async.cg.shared.global [%0], [%1], 16;" :: "r"(dst), "l"(src))
#define CPA_COMMIT()    asm volatile("cp.async.commit_group;" ::: "memory")
#define CPA_WAIT(n)     asm volatile("cp.async.wait_group %0;" :: "n"(n) : "memory")

static __device__ __forceinline__ uint32_t smem_u32(const void* p) {
    uint32_t a;
    asm("{ .reg .u64 t; cvta.to.shared.u64 t, %1; cvt.u32.u64 %0, t; }" : "=r"(a) : "l"(p));
    return a;
}
static __device__ __forceinline__ uint32_t tf32rna(float x) {
    uint32_t r; asm("cvt.rna.tf32.f32 %0, %1;" : "=r"(r) : "f"(x)); return r;
}
static __device__ __forceinline__ uint32_t lds32(uint32_t a) {
    uint32_t v; asm volatile("ld.shared.b32 %0, [%1];" : "=r"(v) : "r"(a)); return v;
}
static __device__ __forceinline__ void mma_tf32(float* c, uint32_t a0, uint32_t a1,
                                                uint32_t a2, uint32_t a3,
                                                uint32_t b0, uint32_t b1) {
    asm volatile(
        "mma.sync.aligned.m16n8k8.row.col.f32.tf32.tf32.f32 "
        "{%0,%1,%2,%3}, {%4,%5,%6,%7}, {%8,%9}, {%0,%1,%2,%3};"
        : "+f"(c[0]), "+f"(c[1]), "+f"(c[2]), "+f"(c[3])
        : "r"(a0), "r"(a1), "r"(a2), "r"(a3), "r"(b0), "r"(b1));
}

__global__ __launch_bounds__(NTH, 2)
void attn_hmma(const float* __restrict__ Q, const float* __restrict__ K,
               const float* __restrict__ V, const int* __restrict__ M,
               float* __restrict__ O)
{
    extern __shared__ char smem[];
    const uint32_t sb = smem_u32(smem);
    const int tid  = threadIdx.x;
    const int w    = tid >> 5;
    const int lane = tid & 31;
    const int q4   = lane & 3;        // quad lane
    const int r4   = lane >> 2;       // 0..7
    const int b    = blockIdx.y;
    const int q0   = blockIdx.x * BM;

    const float* Qb = Q + ((size_t)b * TO_ + q0) * D_;
    const float* Kb = K + (size_t)b * TI_ * D_;
    const float* Vb = V + (size_t)b * TI_ * D_;
    const int*   Mb = M + ((size_t)b * TO_ + q0) * TI_;
    float*       Ob = O + ((size_t)b * TO_ + q0) * D_;

    // ---- stage K/V tile 0 into buffer 0 ----
#pragma unroll
    for (int i = 0; i < 4; i++) {
        int idx = tid + i * NTH;            // 0..1023
        int row = idx >> 4;
        int c4  = idx & 15;
        CPA16(sb + row * 272 + c4 * 16,          (const char*)(Kb + (size_t)row * D_) + c4 * 16);
        CPA16(sb + 17408 + row * 272 + c4 * 16,  (const char*)(Vb + (size_t)row * D_) + c4 * 16);
    }
    CPA_COMMIT();

    // ---- Q fragments (once, scaled, tf32) ----
    uint32_t qa[8][4];
    {
        const float* qp = Qb + (size_t)(w * 16 + r4) * D_ + q4;
#pragma unroll
        for (int kf = 0; kf < 8; kf++) {
            qa[kf][0] = tf32rna(0.125f * qp[kf * 8]);
            qa[kf][1] = tf32rna(0.125f * qp[kf * 8 + 8 * D_]);
            qa[kf][2] = tf32rna(0.125f * qp[kf * 8 + 4]);
            qa[kf][3] = tf32rna(0.125f * qp[kf * 8 + 4 + 8 * D_]);
        }
    }

    float oc[8][4];
#pragma unroll
    for (int nf = 0; nf < 8; nf++)
#pragma unroll
        for (int i = 0; i < 4; i++) oc[nf][i] = 0.f;
    float l0 = 0.f, l1 = 0.f;

    CPA_WAIT(0);
    __syncthreads();

    for (int t = 0; t < NT; t++) {
        const uint32_t sK = sb + (uint32_t)(t & 1) * 34816;
        const uint32_t sV = sK + 17408;

        // stage mask(t) — group 1
        {
            const char* Mg = (const char*)(Mb + (size_t)t * BN);
#pragma unroll
            for (int i = 0; i < 8; i++) {
                int chunk = tid + i * NTH;   // 0..2047
                int row = chunk >> 4;
                int c4  = chunk & 15;
                CPA16(sb + SM_M + row * 272 + c4 * 16, Mg + (size_t)row * (TI_ * 4) + c4 * 16);
            }
        }
        CPA_COMMIT();
        // stage K/V(t+1) — group 2
        if (t + 1 < NT) {
            const uint32_t sKn = sb + (uint32_t)((t + 1) & 1) * 34816;
            const float* Kg = Kb + (size_t)(t + 1) * BN * D_;
            const float* Vg = Vb + (size_t)(t + 1) * BN * D_;
#pragma unroll
            for (int i = 0; i < 4; i++) {
                int idx = tid + i * NTH;
                int row = idx >> 4;
                int c4  = idx & 15;
                CPA16(sKn + row * 272 + c4 * 16,         (const char*)(Kg + (size_t)row * D_) + c4 * 16);
                CPA16(sKn + 17408 + row * 272 + c4 * 16, (const char*)(Vg + (size_t)row * D_) + c4 * 16);
            }
        }
        CPA_COMMIT();

        // ---- GEMM1: S = Q K^T  (C frags sc[nf]) ----
        float sc[8][4];
#pragma unroll
        for (int nf = 0; nf < 8; nf++)
#pragma unroll
            for (int i = 0; i < 4; i++) sc[nf][i] = 0.f;

#pragma unroll
        for (int kf = 0; kf < 8; kf++) {
#pragma unroll
            for (int nf = 0; nf < 8; nf++) {
                uint32_t ka = sK + (uint32_t)(nf * 8 + r4) * 272 + (uint32_t)(kf * 8 + q4) * 4;
                uint32_t b0 = lds32(ka);
                uint32_t b1 = lds32(ka + 16);
                mma_tf32(sc[nf], qa[kf][0], qa[kf][1], qa[kf][2], qa[kf][3], b0, b1);
            }
        }

        CPA_WAIT(1);          // mask group done (KV prefetch still in flight)
        __syncthreads();

        // ---- mask + exp + tf32 (P stays in sc) ----
        {
            const uint32_t mbase = sb + SM_M + (uint32_t)(w * 16 + r4) * 272 + (uint32_t)(2 * q4) * 4;
#pragma unroll
            for (int nf = 0; nf < 8; nf++) {
                const uint32_t ma = mbase + nf * 32;
                const int2 mlo = *(const int2*)(smem + (ma - sb));
                const int2 mhi = *(const int2*)(smem + (ma - sb) + 8 * 272);
                float p0 = (mlo.x != 0) ? __expf(sc[nf][0]) : 0.f;
                float p1 = (mlo.y != 0) ? __expf(sc[nf][1]) : 0.f;
                float p2 = (mhi.x != 0) ? __expf(sc[nf][2]) : 0.f;
                float p3 = (mhi.y != 0) ? __expf(sc[nf][3]) : 0.f;
                l0 += p0 + p1;
                l1 += p2 + p3;
                sc[nf][0] = __uint_as_float(tf32rna(p0));
                sc[nf][1] = __uint_as_float(tf32rna(p1));
                sc[nf][2] = __uint_as_float(tf32rna(p2));
                sc[nf][3] = __uint_as_float(tf32rna(p3));
            }
        }

        // ---- GEMM2: O += P V  (P C-frag -> A-frag via quad shuffles) ----
        const int s0 = (lane & ~3) | (q4 >> 1);
        const int s2 = s0 + 2;
        const bool odd = (q4 & 1) != 0;
#pragma unroll
        for (int kf = 0; kf < 8; kf++) {
            float t00 = __shfl_sync(0xffffffffu, sc[kf][0], s0);
            float t01 = __shfl_sync(0xffffffffu, sc[kf][1], s0);
            float t10 = __shfl_sync(0xffffffffu, sc[kf][2], s0);
            float t11 = __shfl_sync(0xffffffffu, sc[kf][3], s0);
            float t20 = __shfl_sync(0xffffffffu, sc[kf][0], s2);
            float t21 = __shfl_sync(0xffffffffu, sc[kf][1], s2);
            float t30 = __shfl_sync(0xffffffffu, sc[kf][2], s2);
            float t31 = __shfl_sync(0xffffffffu, sc[kf][3], s2);
            uint32_t a0 = __float_as_uint(odd ? t01 : t00);
            uint32_t a1 = __float_as_uint(odd ? t11 : t10);
            uint32_t a2 = __float_as_uint(odd ? t21 : t20);
            uint32_t a3 = __float_as_uint(odd ? t31 : t30);
#pragma unroll
            for (int nf = 0; nf < 8; nf++) {
                uint32_t va = sV + (uint32_t)(kf * 8 + q4) * 272 + (uint32_t)(nf * 8 + r4) * 4;
                uint32_t b0 = lds32(va);
                uint32_t b1 = lds32(va + 4 * 272);
                mma_tf32(oc[nf], a0, a1, a2, a3, b0, b1);
            }
        }

        CPA_WAIT(0);          // KV(t+1) landed; mask buffer free for rewrite
        __syncthreads();
    }

    // ---- epilogue: row sums + normalize + store ----
    l0 += __shfl_xor_sync(0xffffffffu, l0, 1);
    l0 += __shfl_xor_sync(0xffffffffu, l0, 2);
    l1 += __shfl_xor_sync(0xffffffffu, l1, 1);
    l1 += __shfl_xor_sync(0xffffffffu, l1, 2);
    const float inv0 = 1.f / l0;
    const float inv1 = 1.f / l1;

    float* orow0 = Ob + (size_t)(w * 16 + r4) * D_ + 2 * q4;
    float* orow1 = orow0 + 8 * D_;
#pragma unroll
    for (int nf = 0; nf < 8; nf++) {
        float2 v0 = make_float2(oc[nf][0] * inv0, oc[nf][1] * inv0);
        float2 v1 = make_float2(oc[nf][2] * inv1, oc[nf][3] * inv1);
        *(float2*)(orow0 + nf * 8) = v0;
        *(float2*)(orow1 + nf * 8) = v1;
    }
}

extern "C" void kernel_launch(void* const* d_in, const int* in_sizes, int n_in,
                              void* d_out, int out_size) {
    const float* q = (const float*)d_in[0];
    const float* k = (const float*)d_in[1];
    const float* v = (const float*)d_in[2];
    const int*   m = (const int*)d_in[3];
    float* o = (float*)d_out;

    cudaFuncSetAttribute(attn_hmma, cudaFuncAttributeMaxDynamicSharedMemorySize, SMEM_BYTES);
    dim3 grid(TO_ / BM, B_);
    attn_hmma<<<grid, NTH, SMEM_BYTES>>>(q, k, v, m, o);
}